// round 1
// baseline (speedup 1.0000x reference)
#include <cuda_runtime.h>

// Problem constants (shapes fixed by the dataset; N/E re-derived at runtime)
#define NMAX 50000
#define EMAX 800000
// D = 128, ED = 64, H = 4, U = 32, HU = 128

// ---- scratch (device globals: allocation-free per harness rules) ----
__device__ float g_q [NMAX * 128];
__device__ float g_k [NMAX * 128];
__device__ float g_v [NMAX * 128];
__device__ float g_mk[NMAX * 256];   // Mk[n][h*64 + c]
__device__ float g_kb[NMAX * 4];     // kb[n][h]
__device__ int   g_rowptr[NMAX + 1];

// ============================================================================
// K1: q,k,v = X @ W{q,k,v} + b   — [N,128] @ [128,128], blockIdx.y selects matrix
//     BM=128, BN=128, BK=32, 256 threads, 8x8 register tile
// ============================================================================
__global__ __launch_bounds__(256) void qkv_gemm_kernel(
    const float* __restrict__ X,
    const float* __restrict__ Wq, const float* __restrict__ bq,
    const float* __restrict__ Wk, const float* __restrict__ bk,
    const float* __restrict__ Wv, const float* __restrict__ bv,
    int N)
{
    __shared__ float As[32][129];   // [k][m], padded: conflict-free stores
    __shared__ float Bs[32][128];   // [k][n]

    const float* W; const float* bias; float* Out;
    if (blockIdx.y == 0)      { W = Wq; bias = bq; Out = g_q; }
    else if (blockIdx.y == 1) { W = Wk; bias = bk; Out = g_k; }
    else                      { W = Wv; bias = bv; Out = g_v; }

    const int row0 = blockIdx.x * 128;
    const int tid  = threadIdx.x;
    const int tx   = tid & 15;    // m-group
    const int ty   = tid >> 4;    // n-group

    float acc[8][8];
#pragma unroll
    for (int i = 0; i < 8; i++)
#pragma unroll
        for (int j = 0; j < 8; j++) acc[i][j] = 0.f;

    for (int kt = 0; kt < 128; kt += 32) {
        // load A tile (transposed into As[k][m])
#pragma unroll
        for (int i = 0; i < 4; i++) {
            int r = (tid >> 3) + i * 32;
            int c = (tid & 7) * 4;
            float4 a = make_float4(0.f, 0.f, 0.f, 0.f);
            if (row0 + r < N)
                a = *(const float4*)(X + (row0 + r) * 128 + kt + c);
            As[c + 0][r] = a.x;
            As[c + 1][r] = a.y;
            As[c + 2][r] = a.z;
            As[c + 3][r] = a.w;
        }
        // load B tile
#pragma unroll
        for (int i = 0; i < 4; i++) {
            int kk = (tid >> 5) + i * 8;
            int nn = (tid & 31) * 4;
            *(float4*)&Bs[kk][nn] = *(const float4*)(W + (kt + kk) * 128 + nn);
        }
        __syncthreads();
#pragma unroll
        for (int k = 0; k < 32; k++) {
            float a[8], b[8];
#pragma unroll
            for (int i = 0; i < 8; i++) a[i] = As[k][tx * 8 + i];
            *(float4*)&b[0] = *(float4*)&Bs[k][ty * 8];
            *(float4*)&b[4] = *(float4*)&Bs[k][ty * 8 + 4];
#pragma unroll
            for (int i = 0; i < 8; i++)
#pragma unroll
                for (int j = 0; j < 8; j++)
                    acc[i][j] = fmaf(a[i], b[j], acc[i][j]);
        }
        __syncthreads();
    }

#pragma unroll
    for (int i = 0; i < 8; i++) {
        int r = row0 + tx * 8 + i;
        if (r < N) {
            float4 o0, o1;
            o0.x = acc[i][0] + bias[ty * 8 + 0];
            o0.y = acc[i][1] + bias[ty * 8 + 1];
            o0.z = acc[i][2] + bias[ty * 8 + 2];
            o0.w = acc[i][3] + bias[ty * 8 + 3];
            o1.x = acc[i][4] + bias[ty * 8 + 4];
            o1.y = acc[i][5] + bias[ty * 8 + 5];
            o1.z = acc[i][6] + bias[ty * 8 + 6];
            o1.w = acc[i][7] + bias[ty * 8 + 7];
            *(float4*)(Out + r * 128 + ty * 8)     = o0;
            *(float4*)(Out + r * 128 + ty * 8 + 4) = o1;
        }
    }
}

// ============================================================================
// K2: Mk[n,h,c] = sum_u We[c, h*32+u] * k[n,h,u];  kb[n,h] = sum_u be[hu]*k[n,h,u]
//     block = 256 threads (h = tid/64, c = tid%64), 16 nodes per block
// ============================================================================
__global__ __launch_bounds__(256) void mk_kernel(
    const float* __restrict__ We, const float* __restrict__ be, int N)
{
    __shared__ float WeT[128][65];   // [hu][c], padded
    __shared__ float ks[16][128];

    const int tid = threadIdx.x;
    const int n0  = blockIdx.x * 16;

    // transpose We (64x128 row-major) into WeT[hu][c]
    for (int i = tid; i < 64 * 128; i += 256) {
        int c  = i >> 7;
        int hu = i & 127;
        WeT[hu][c] = We[i];
    }
    // load 16 nodes of k
    for (int i = tid; i < 16 * 128 / 4; i += 256) {
        int nl  = i >> 5;
        int off = (i & 31) * 4;
        float4 val = make_float4(0.f, 0.f, 0.f, 0.f);
        if (n0 + nl < N) val = *(const float4*)(g_k + (n0 + nl) * 128 + off);
        *(float4*)&ks[nl][off] = val;
    }
    __syncthreads();

    const int h = tid >> 6, c = tid & 63;
#pragma unroll 1
    for (int nl = 0; nl < 16; nl++) {
        if (n0 + nl >= N) break;
        float s = 0.f;
#pragma unroll
        for (int u = 0; u < 32; u++)
            s = fmaf(ks[nl][h * 32 + u], WeT[h * 32 + u][c], s);
        g_mk[(n0 + nl) * 256 + h * 64 + c] = s;
    }
    if (tid < 64) {
        int nl = tid >> 2, h2 = tid & 3;
        if (n0 + nl < N) {
            float s = 0.f;
#pragma unroll
            for (int u = 0; u < 32; u++)
                s = fmaf(be[h2 * 32 + u], ks[nl][h2 * 32 + u], s);
            g_kb[(n0 + nl) * 4 + h2] = s;
        }
    }
}

// ============================================================================
// K3: rowptr[n] = lower_bound(src, n)  (src sorted)
// ============================================================================
__global__ void rowptr_kernel(const int* __restrict__ src, int E, int N)
{
    int n = blockIdx.x * blockDim.x + threadIdx.x;
    if (n > N) return;
    int lo = 0, hi = E;
    while (lo < hi) {
        int mid = (lo + hi) >> 1;
        if (src[mid] < n) lo = mid + 1; else hi = mid;
    }
    g_rowptr[n] = lo;
}

// ============================================================================
// K4: fused per-node edge pass — one warp per source node.
//     Online softmax + attn-weighted v aggregation + output GEMM epilogue.
//     lane l owns hu = 4l..4l+3 (head hl = l/8).
// ============================================================================
__global__ __launch_bounds__(256) void edge_attn_kernel(
    const float* __restrict__ EF, const int* __restrict__ dst,
    const float* __restrict__ Wo, const float* __restrict__ bo,
    float* __restrict__ out, int N)
{
    __shared__ float sWo[128 * 32];
    __shared__ float sbo[32];
    const int tid = threadIdx.x;
    for (int i = tid; i < 1024; i += 256)
        ((float4*)sWo)[i] = ((const float4*)Wo)[i];
    if (tid < 32) sbo[tid] = bo[tid];
    __syncthreads();

    const int lane = tid & 31, warp = tid >> 5;
    const int n = blockIdx.x * 8 + warp;
    if (n >= N) return;

    const int hl = lane >> 3;
    const float4 q4 = *(const float4*)(g_q + n * 128 + lane * 4);
    const int e0 = g_rowptr[n], e1 = g_rowptr[n + 1];

    float  m    = -1e30f;
    float  sexp = 0.f;
    float4 acc  = make_float4(0.f, 0.f, 0.f, 0.f);

    for (int e = e0; e < e1; e++) {
        const int d = dst[e];
        const float4 k4 = *(const float4*)(g_k + d * 128 + lane * 4);

        // q·k partial, reduced within each 8-lane head group
        float t1 = q4.x * k4.x + q4.y * k4.y + q4.z * k4.z + q4.w * k4.w;
        t1 += __shfl_xor_sync(0xffffffffu, t1, 1);
        t1 += __shfl_xor_sync(0xffffffffu, t1, 2);
        t1 += __shfl_xor_sync(0xffffffffu, t1, 4);

        // edge-feature term: sum_c ef[c] * Mk[d, h, c] (c = lane, lane+32)
        const float ef1 = EF[e * 64 + lane];
        const float ef2 = EF[e * 64 + 32 + lane];
        const float* mk = g_mk + d * 256;
        float px = fmaf(ef1, mk[  0 + lane], ef2 * mk[ 32 + lane]);
        float py = fmaf(ef1, mk[ 64 + lane], ef2 * mk[ 96 + lane]);
        float pz = fmaf(ef1, mk[128 + lane], ef2 * mk[160 + lane]);
        float pw = fmaf(ef1, mk[192 + lane], ef2 * mk[224 + lane]);
#pragma unroll
        for (int o = 16; o >= 1; o >>= 1) {
            px += __shfl_xor_sync(0xffffffffu, px, o);
            py += __shfl_xor_sync(0xffffffffu, py, o);
            pz += __shfl_xor_sync(0xffffffffu, pz, o);
            pw += __shfl_xor_sync(0xffffffffu, pw, o);
        }
        const float t2 = (hl < 2) ? (hl == 0 ? px : py) : (hl == 2 ? pz : pw);
        const float s  = t1 + t2 + g_kb[d * 4 + hl];

        // online softmax update
        const float mnew  = fmaxf(m, s);
        const float scale = __expf(m - mnew);
        const float w     = __expf(s - mnew);
        const float4 v4 = *(const float4*)(g_v + d * 128 + lane * 4);
        sexp  = fmaf(sexp,  scale, w);
        acc.x = fmaf(acc.x, scale, w * v4.x);
        acc.y = fmaf(acc.y, scale, w * v4.y);
        acc.z = fmaf(acc.z, scale, w * v4.z);
        acc.w = fmaf(acc.w, scale, w * v4.w);
        m = mnew;
    }

    const float inv = (sexp > 0.f) ? (1.0f / sexp) : 0.f;
    acc.x *= inv; acc.y *= inv; acc.z *= inv; acc.w *= inv;

    // output epilogue: out[n, j=lane] = relu(sum_hu attended[hu]*Wo[hu,j] + bo[j])
    float o = sbo[lane];
#pragma unroll
    for (int p = 0; p < 32; p++) {
        const float ax = __shfl_sync(0xffffffffu, acc.x, p);
        const float ay = __shfl_sync(0xffffffffu, acc.y, p);
        const float az = __shfl_sync(0xffffffffu, acc.z, p);
        const float aw = __shfl_sync(0xffffffffu, acc.w, p);
        o = fmaf(ax, sWo[(4 * p + 0) * 32 + lane], o);
        o = fmaf(ay, sWo[(4 * p + 1) * 32 + lane], o);
        o = fmaf(az, sWo[(4 * p + 2) * 32 + lane], o);
        o = fmaf(aw, sWo[(4 * p + 3) * 32 + lane], o);
    }
    out[n * 32 + lane] = fmaxf(o, 0.f);
}

// ============================================================================
// launch
// ============================================================================
extern "C" void kernel_launch(void* const* d_in, const int* in_sizes, int n_in,
                              void* d_out, int out_size)
{
    const float* X  = (const float*)d_in[0];
    const int*   EI = (const int*)  d_in[1];   // [2,E]: src then dst
    const float* EF = (const float*)d_in[2];
    const float* Wq = (const float*)d_in[3];
    const float* bq = (const float*)d_in[4];
    const float* Wk = (const float*)d_in[5];
    const float* bk = (const float*)d_in[6];
    const float* Wv = (const float*)d_in[7];
    const float* bv = (const float*)d_in[8];
    const float* We = (const float*)d_in[9];
    const float* be = (const float*)d_in[10];
    const float* Wo = (const float*)d_in[11];
    const float* bo = (const float*)d_in[12];

    const int N = in_sizes[0] / 128;
    const int E = in_sizes[1] / 2;

    dim3 g1((N + 127) / 128, 3);
    qkv_gemm_kernel<<<g1, 256>>>(X, Wq, bq, Wk, bk, Wv, bv, N);
    mk_kernel<<<(N + 15) / 16, 256>>>(We, be, N);
    rowptr_kernel<<<(N + 1 + 255) / 256, 256>>>(EI, E, N);
    edge_attn_kernel<<<(N + 7) / 8, 256>>>(EF, EI + E, Wo, bo, (float*)d_out, N);
}